// round 13
// baseline (speedup 1.0000x reference)
#include <cuda_runtime.h>
#include <cstdint>

#define Bn 4
#define Cn 7
#define Hn 512
#define Wn 1024
#define HW (Hn*Wn)
#define NID 7
#define NBINS 2048
#define BIN_SCALE 1024.0f             /* e-hist: NBINS / 2.0, e in [0,2] */
#define QMAX 2.0f                     /* neg q-hist range; q>QMAX dropped (bounded tail) */
#define QBIN_SCALE (NBINS/QMAX)       /* 1024 */
#define XSTEP (2.0f/2047.0f)
#define YSTEP (1.0f/1023.0f)
#define P1_BLK 256
#define NBLK1 (P1_BLK*Bn)
#define STRIDE4 (P1_BLK*256)          /* 65536 float4-threads per batch -> 2 iters */

// ---- scratch (static device memory; zero at load; every run re-zeroes) ----
// hist[i].x = NEG count binned by q; hist[i].y = POS count binned by e
__device__ unsigned g_hist[Bn*NID*NBINS*2];   // 0.46MB
__device__ double   g_stats[Bn*NID*7];        // cnt, Sx, Sy, Ss0, Ss1, Sq, pad
__device__ float    g_params[Bn*NID*4];       // c0, c1, sexp0, sexp1
__device__ double   g_cls[Bn*4];              // focal_sum, valid_cnt, seed_bg, seedfg_sum
__device__ float    g_instl[Bn*NID];
__device__ unsigned g_c1, g_c2;               // completion counters

// ------------------------------------------------------------------
// Phase 1: per-(b,id) stats. Vector loads; counts packed 4-bit x7.
__global__ __launch_bounds__(256) void phase1_kernel(
        const float* __restrict__ pred, const int* __restrict__ inst) {
    __shared__ float sh[NID*6];
    __shared__ unsigned s_done;
    int tid = threadIdx.x;
    int lane = tid & 31;
    if (tid < NID*6) sh[tid] = 0.f;
    __syncthreads();

    float acc[NID][5];                 // Sx, Sy, Ss0, Ss1, Sq
    #pragma unroll
    for (int id = 0; id < NID; id++)
        #pragma unroll
        for (int k = 0; k < 5; k++) acc[id][k] = 0.f;
    unsigned cntp = 0u;                // 7 x 4-bit counters

    int b = blockIdx.y;
    const float4* s0p = (const float4*)(pred + ((size_t)b*Cn + 2)*HW);
    const float4* s1p = (const float4*)(pred + ((size_t)b*Cn + 3)*HW);
    const int4*   ip  = (const int4*)(inst + (size_t)b*HW);

    int base = blockIdx.x*blockDim.x + tid;

    #pragma unroll
    for (int k = 0; k < 2; k++) {
        int j = base + k*STRIDE4;
        int4   v4 = ip[j];
        float4 a4 = s0p[j];
        float4 c4 = s1p[j];
        int   vv[4] = {v4.x, v4.y, v4.z, v4.w};
        float aa[4] = {a4.x, a4.y, a4.z, a4.w};
        float cc[4] = {c4.x, c4.y, c4.z, c4.w};
        #pragma unroll
        for (int e = 0; e < 4; e++) {
            int v = vv[e];
            if (v >= 1) {
                int i = 4*j + e;
                cntp += 1u << (4*(v-1));
                float x = (float)(i & (Wn-1)) * XSTEP;
                float y = (float)(i >> 10)    * YSTEP;
                float a = aa[e], c = cc[e];
                float q2 = fmaf(a, a, c*c);
                #pragma unroll
                for (int id = 0; id < NID; id++) {
                    float m = (v == id+1) ? 1.f : 0.f;
                    acc[id][0] = fmaf(m, x,  acc[id][0]);
                    acc[id][1] = fmaf(m, y,  acc[id][1]);
                    acc[id][2] = fmaf(m, a,  acc[id][2]);
                    acc[id][3] = fmaf(m, c,  acc[id][3]);
                    acc[id][4] = fmaf(m, q2, acc[id][4]);
                }
            }
        }
    }

    float vals[NID*6];
    #pragma unroll
    for (int id = 0; id < NID; id++) {
        vals[id*6+0] = (float)((cntp >> (4*id)) & 0xFu);
        #pragma unroll
        for (int k = 0; k < 5; k++) vals[id*6+1+k] = acc[id][k];
    }
    #pragma unroll
    for (int o = 16; o > 0; o >>= 1)
        #pragma unroll
        for (int k = 0; k < NID*6; k++)
            vals[k] += __shfl_down_sync(0xffffffffu, vals[k], o);
    if (lane == 0)
        #pragma unroll
        for (int k = 0; k < NID*6; k++) atomicAdd(&sh[k], vals[k]);
    __syncthreads();
    if (tid < NID*6) {
        int id = tid / 6, slot = tid % 6;
        atomicAdd(&g_stats[b*NID*7 + id*7 + slot], (double)sh[tid]);
    }

    __threadfence();
    if (tid == 0) s_done = atomicAdd(&g_c1, 1u);
    __syncthreads();
    if (s_done == NBLK1 - 1) {
        if (tid < Bn*NID) {
            const double* s = &g_stats[tid*7];
            double cnt = s[0];
            double cn = cnt > 1.0 ? cnt : 1.0;
            g_params[tid*4+0] = (float)(s[1]/cn);
            g_params[tid*4+1] = (float)(s[2]/cn);
            g_params[tid*4+2] = (float)exp(10.0 * s[3]/cn);
            g_params[tid*4+3] = (float)exp(10.0 * s[4]/cn);
        }
        if (tid == 0) g_c1 = 0u;
    }
}

// ------------------------------------------------------------------
__device__ __forceinline__ float tanh_fast(float x) {
    float r;
    asm("tanh.approx.f32 %0, %1;" : "=f"(r) : "f"(x));
    return r;
}

__device__ __forceinline__ uint32_t smem_u32(const void* p) {
    uint32_t a;
    asm("{ .reg .u64 t; cvta.to.shared.u64 t, %1; cvt.u32.u64 %0, t; }"
        : "=r"(a) : "l"(p));
    return a;
}

// Phase 2: pos handling hoisted out of the id loop (once per pixel: the only
// dist-exp + e-bin + seed_fg). Id loop: ONE single-condition arm, q-bin, no exp.
__global__ __launch_bounds__(256, 4) void phase2_kernel(
        const float* __restrict__ pred, const int* __restrict__ inst,
        const int* __restrict__ lab) {
    __shared__ float4 sprm[NID];
    __shared__ float sh[4];
    int tid = threadIdx.x;
    int lane = tid & 31;
    int b = blockIdx.y;
    if (tid < 4) sh[tid] = 0.f;
    if (tid < NID) sprm[tid] = __ldg(((const float4*)g_params) + b*NID + tid);
    __syncthreads();
    uint32_t prm_a = smem_u32(sprm);

    const float4* p0p = (const float4*)(pred + ((size_t)b*Cn + 0)*HW);
    const float4* p1p = (const float4*)(pred + ((size_t)b*Cn + 1)*HW);
    const float4* p4p = (const float4*)(pred + ((size_t)b*Cn + 4)*HW);
    const float4* p5p = (const float4*)(pred + ((size_t)b*Cn + 5)*HW);
    const float4* p6p = (const float4*)(pred + ((size_t)b*Cn + 6)*HW);
    const int4*   ip  = (const int4*)(inst + (size_t)b*HW);
    const int4*   lp  = (const int4*)(lab  + (size_t)b*HW);
    unsigned* hb = g_hist + (size_t)b*NID*NBINS*2;

    float sfgS = 0.f, clsS = 0.f, vcnt = 0.f, sbg = 0.f;

    int base = blockIdx.x*blockDim.x + tid;
    #pragma unroll
    for (int k = 0; k < 2; k++) {
        int j = base + k*STRIDE4;
        int4   v4 = ip[j];
        int4   l4 = lp[j];
        float4 b0 = p0p[j];
        float4 b1 = p1p[j];
        float4 b4 = p4p[j];
        float4 b5 = p5p[j];
        float4 b6 = p6p[j];
        int   vv[4] = {v4.x, v4.y, v4.z, v4.w};
        int   ll[4] = {l4.x, l4.y, l4.z, l4.w};
        float f0[4] = {b0.x, b0.y, b0.z, b0.w};
        float f1[4] = {b1.x, b1.y, b1.z, b1.w};
        float f4[4] = {b4.x, b4.y, b4.z, b4.w};
        float f5[4] = {b5.x, b5.y, b5.z, b5.w};
        float f6[4] = {b6.x, b6.y, b6.z, b6.w};

        #pragma unroll
        for (int e = 0; e < 4; e++) {
            int i = 4*j + e;
            int v = vv[e];
            int l = ll[e];
            float x = (float)(i & (Wn-1)) * XSTEP;
            float y = (float)(i >> 10)    * YSTEP;
            float e0 = tanh_fast(f0[e]) + x;
            float e1 = tanh_fast(f1[e]) + y;
            float seed = fmaf(0.5f, tanh_fast(0.5f*f4[e]), 0.5f);

            // pos arm: once per pixel, dynamic-indexed params
            if (v >= 1) {
                float px, py, pz, pw;
                asm volatile("ld.shared.v4.f32 {%0,%1,%2,%3}, [%4];"
                    : "=f"(px), "=f"(py), "=f"(pz), "=f"(pw)
                    : "r"(prm_a + (v-1)*16));
                float dx = e0 - px;
                float dy = e1 - py;
                float q  = fmaf(dx*dx, pz, dy*dy*pw);
                float d  = __expf(-q);
                int bin = (int)(fmaf(-2.f, d, 2.f) * BIN_SCALE);
                bin = bin < NBINS-1 ? bin : NBINS-1;
                bin = bin > 0 ? bin : 0;
                atomicAdd(hb + (((size_t)(v-1)*NBINS + bin) << 1) + 1, 1u);
                float df = seed - d;
                sfgS = fmaf(df, df, sfgS);
            }

            // neg loop: single-condition arm, q-binned, NO exp
            #pragma unroll
            for (int id = 0; id < NID; id++) {
                float px, py, pz, pw;
                asm volatile("ld.shared.v4.f32 {%0,%1,%2,%3}, [%4];"
                    : "=f"(px), "=f"(py), "=f"(pz), "=f"(pw)
                    : "r"(prm_a + id*16));
                float dx = e0 - px;
                float dy = e1 - py;
                float q  = fmaf(dx*dx, pz, dy*dy*pw);
                if ((v != id + 1) && (q < QMAX)) {
                    int bin = (int)(q * QBIN_SCALE);    // 0..2047
                    atomicAdd(hb + (((size_t)id*NBINS + bin) << 1), 1u);
                }
            }

            if (l < 2) {
                float xa = f5[e], xb = f6[e];
                float xt = l ? xb : xa;
                float xo = l ? xa : xb;
                float u = __expf(xo - xt);
                float logpt = -__logf(1.f + u);
                float pt = __fdividef(1.f, 1.f + u);
                float om = 1.f - pt;
                clsS += -om*om*logpt;
                vcnt += 1.f;
            }
            if (l == 0) sbg += seed*seed;
        }
    }

    float vals[4] = {clsS, vcnt, sbg, sfgS};
    #pragma unroll
    for (int o = 16; o > 0; o >>= 1)
        #pragma unroll
        for (int k = 0; k < 4; k++)
            vals[k] += __shfl_down_sync(0xffffffffu, vals[k], o);
    if (lane == 0)
        #pragma unroll
        for (int k = 0; k < 4; k++) atomicAdd(&sh[k], vals[k]);
    __syncthreads();
    if (tid < 4) atomicAdd(&g_cls[b*4 + tid], (double)sh[tid]);
}

// ------------------------------------------------------------------
// Scan + final: stage hist, remap neg q-bins to e-bins (2048 exps/block),
// then descending-e Lovasz walk. Last block reduces + resets state.
__global__ __launch_bounds__(512) void scan_kernel(float* out) {
    __shared__ uint2 hs[NBINS];               // 16KB unified e-hist
    __shared__ unsigned negq[NBINS];          // 8KB staged q-hist
    __shared__ unsigned sp[512], sn[512];
    __shared__ float red[16];
    __shared__ unsigned s_done;
    __shared__ double shP[Bn*NID], shV[Bn*NID], shI[Bn*NID];
    int t = threadIdx.x;
    int bi = blockIdx.x;                       // 0..27
    uint2* h = (uint2*)g_hist + (size_t)bi*NBINS;

    for (int i = t; i < NBINS; i += 512) {     // coalesced stage + clear
        uint2 c = h[i];
        h[i] = make_uint2(0u, 0u);
        hs[i] = make_uint2(0u, c.y);           // pos counts already e-binned
        negq[i] = c.x;
    }
    __syncthreads();
    for (int i = t; i < NBINS; i += 512) {     // remap neg q-bin -> e-bin
        unsigned c = negq[i];
        if (c) {
            float qc = ((float)i + 0.5f) * (QMAX / (float)NBINS);
            float ev = 2.f * __expf(-qc);
            int jj = (int)(ev * BIN_SCALE);
            jj = jj < NBINS-1 ? jj : NBINS-1;
            atomicAdd(&((unsigned*)hs)[jj*2], c);   // hs[jj].x
        }
    }
    __syncthreads();

    const int BPT = NBINS/512;                 // 4 bins per thread
    unsigned lp = 0, ln = 0;
    int r0 = t * BPT;
    #pragma unroll
    for (int k = 0; k < BPT; k++) {
        uint2 c = hs[NBINS-1 - (r0 + k)];
        ln += c.x; lp += c.y;                  // .x = neg, .y = pos
    }
    sp[t] = lp; sn[t] = ln;
    __syncthreads();
    for (int o = 1; o < 512; o <<= 1) {        // Hillis-Steele inclusive scan
        unsigned a = 0, bsum = 0;
        if (t >= o) { a = sp[t-o]; bsum = sn[t-o]; }
        __syncthreads();
        sp[t] += a; sn[t] += bsum;
        __syncthreads();
    }
    unsigned Ptot = sp[511];

    float acc = 0.f;
    if (Ptot > 0) {
        float P = (float)Ptot;
        float p = (float)(sp[t] - lp);         // exclusive prefix (descending)
        float n = (float)(sn[t] - ln);
        const float escale = 2.0f / (float)NBINS;
        #pragma unroll
        for (int k = 0; k < BPT; k++) {
            int bin = NBINS-1 - (r0 + k);
            uint2 c = hs[bin];
            if (c.x | c.y) {
                float cp = (float)c.y, cn = (float)c.x;
                float num = cp*(P + n) + cn*(P - p);
                float den = (P + n) * (P + n + cn);
                float ec  = ((float)bin + 0.5f) * escale;
                acc += ec * __fdividef(num, den);
                p += cp; n += cn;
            }
        }
    }
    #pragma unroll
    for (int o = 16; o > 0; o >>= 1) acc += __shfl_down_sync(0xffffffffu, acc, o);
    if ((t & 31) == 0) red[t >> 5] = acc;
    __syncthreads();
    if (t < 32) {
        float v = (t < 16) ? red[t] : 0.f;
        #pragma unroll
        for (int o = 8; o > 0; o >>= 1) v += __shfl_down_sync(0xffffffffu, v, o);
        if (t == 0) g_instl[bi] = v;
    }

    __threadfence();
    if (t == 0) s_done = atomicAdd(&g_c2, 1u);
    __syncthreads();
    if (s_done != Bn*NID - 1) return;

    if (t < Bn*NID) {
        const double* s = &g_stats[t*7];
        double cnt = s[0];
        double pres = 0.0, var = 0.0, inl = 0.0;
        if (cnt > 0.0) {
            double m0 = s[3]/cnt, m1 = s[4]/cnt;
            pres = 1.0;
            var = (s[5] - cnt*(m0*m0 + m1*m1)) / (2.0*cnt);
            inl = (double)g_instl[t];
        }
        shP[t] = pres; shV[t] = var; shI[t] = inl;
    }
    __syncthreads();
    if (t == 0) {
        double totalL = 0.0, totalC = 0.0;
        for (int b = 0; b < Bn; b++) {
            double obj = 0.0, iS = 0.0, vS = 0.0;
            for (int id = 0; id < NID; id++) {
                int k = b*NID + id;
                obj += shP[k]; iS += shI[k]; vS += shV[k];
            }
            if (obj < 1.0) obj = 1.0;
            double seed_loss = (g_cls[b*4+2] + 200.0*g_cls[b*4+3]) / (double)HW;
            totalL += iS/obj + 10.0*(vS/obj) + seed_loss;
            double vc = g_cls[b*4+1]; if (vc < 1.0) vc = 1.0;
            totalC += g_cls[b*4+0] / vc;
        }
        out[0] = (float)((totalL + totalC) / (double)Bn);
    }
    __syncthreads();
    for (int i = t; i < Bn*NID*7; i += 512) g_stats[i] = 0.0;
    for (int i = t; i < Bn*4;     i += 512) g_cls[i] = 0.0;
    if (t == 0) g_c2 = 0u;
}

// ------------------------------------------------------------------
extern "C" void kernel_launch(void* const* d_in, const int* in_sizes, int n_in,
                              void* d_out, int out_size) {
    const float* pred = (const float*)d_in[0];
    const int*   inst = (const int*)d_in[1];
    const int*   lab  = (const int*)d_in[2];
    float* out = (float*)d_out;

    phase1_kernel<<<dim3(P1_BLK, Bn), 256>>>(pred, inst);
    phase2_kernel<<<dim3(P1_BLK, Bn), 256>>>(pred, inst, lab);
    scan_kernel<<<Bn*NID, 512>>>(out);
}

// round 14
// speedup vs baseline: 1.0425x; 1.0425x over previous
#include <cuda_runtime.h>
#include <cstdint>

#define Bn 4
#define Cn 7
#define Hn 512
#define Wn 1024
#define HW (Hn*Wn)
#define NID 7
#define NBINS 4096
#define BIN_SCALE 2048.0f             /* NBINS / 2.0 : errors live in [0,2] */
#define Q_DROP 2.0f                   /* neg evals with q>2 dropped (bounded tail) */
#define XSTEP (2.0f/2047.0f)
#define YSTEP (1.0f/1023.0f)
#define P1_BLK 512                    /* phase1 blocks per batch: 1 float4/thread */
#define NBLK1 (P1_BLK*Bn)
#define P2_BLK 256                    /* phase2 blocks per batch */
#define STRIDE4 (P2_BLK*256)          /* phase2: 65536 float4-threads -> 2 iters */

// ---- scratch (static device memory; zero at load; every run re-zeroes) ----
__device__ unsigned g_hist[Bn*NID*NBINS*2];   // [b][id][bin][{neg,pos}] 0.92MB
__device__ double   g_stats[Bn*NID*7];        // cnt, Sx, Sy, Ss0, Ss1, Sq, pad
__device__ float    g_params[Bn*NID*4];       // c0, c1, sexp0, sexp1
__device__ double   g_seedfg[Bn*NID];
__device__ double   g_cls[Bn*4];              // focal_sum, valid_cnt, seed_bg, pad
__device__ float    g_instl[Bn*NID];
__device__ unsigned g_c1, g_c2;               // completion counters

// ------------------------------------------------------------------
// Phase 1: ONE float4 per thread (512 blk/batch x 256 thr = HW/4).
// Counts packed 4-bit x7 (max 4 px/thread). Last block preps params.
__global__ __launch_bounds__(256) void phase1_kernel(
        const float* __restrict__ pred, const int* __restrict__ inst) {
    __shared__ float sh[NID*6];
    __shared__ unsigned s_done;
    int tid = threadIdx.x;
    int lane = tid & 31;
    if (tid < NID*6) sh[tid] = 0.f;
    __syncthreads();

    float acc[NID][5];                 // Sx, Sy, Ss0, Ss1, Sq
    #pragma unroll
    for (int id = 0; id < NID; id++)
        #pragma unroll
        for (int k = 0; k < 5; k++) acc[id][k] = 0.f;
    unsigned cntp = 0u;                // 7 x 4-bit counters

    int b = blockIdx.y;
    const float4* s0p = (const float4*)(pred + ((size_t)b*Cn + 2)*HW);
    const float4* s1p = (const float4*)(pred + ((size_t)b*Cn + 3)*HW);
    const int4*   ip  = (const int4*)(inst + (size_t)b*HW);

    int j = blockIdx.x*blockDim.x + tid;
    {
        int4   v4 = ip[j];
        float4 a4 = s0p[j];
        float4 c4 = s1p[j];
        int   vv[4] = {v4.x, v4.y, v4.z, v4.w};
        float aa[4] = {a4.x, a4.y, a4.z, a4.w};
        float cc[4] = {c4.x, c4.y, c4.z, c4.w};
        #pragma unroll
        for (int e = 0; e < 4; e++) {
            int v = vv[e];
            if (v >= 1) {
                int i = 4*j + e;
                cntp += 1u << (4*(v-1));
                float x = (float)(i & (Wn-1)) * XSTEP;
                float y = (float)(i >> 10)    * YSTEP;
                float a = aa[e], c = cc[e];
                float q2 = fmaf(a, a, c*c);
                #pragma unroll
                for (int id = 0; id < NID; id++) {
                    float m = (v == id+1) ? 1.f : 0.f;
                    acc[id][0] = fmaf(m, x,  acc[id][0]);
                    acc[id][1] = fmaf(m, y,  acc[id][1]);
                    acc[id][2] = fmaf(m, a,  acc[id][2]);
                    acc[id][3] = fmaf(m, c,  acc[id][3]);
                    acc[id][4] = fmaf(m, q2, acc[id][4]);
                }
            }
        }
    }

    float vals[NID*6];
    #pragma unroll
    for (int id = 0; id < NID; id++) {
        vals[id*6+0] = (float)((cntp >> (4*id)) & 0xFu);
        #pragma unroll
        for (int k = 0; k < 5; k++) vals[id*6+1+k] = acc[id][k];
    }
    #pragma unroll
    for (int o = 16; o > 0; o >>= 1)
        #pragma unroll
        for (int k = 0; k < NID*6; k++)
            vals[k] += __shfl_down_sync(0xffffffffu, vals[k], o);
    if (lane == 0)
        #pragma unroll
        for (int k = 0; k < NID*6; k++) atomicAdd(&sh[k], vals[k]);
    __syncthreads();
    if (tid < NID*6) {
        int id = tid / 6, slot = tid % 6;
        atomicAdd(&g_stats[b*NID*7 + id*7 + slot], (double)sh[tid]);
    }

    __threadfence();
    if (tid == 0) s_done = atomicAdd(&g_c1, 1u);
    __syncthreads();
    if (s_done == NBLK1 - 1) {
        if (tid < Bn*NID) {
            const double* s = &g_stats[tid*7];
            double cnt = s[0];
            double cn = cnt > 1.0 ? cnt : 1.0;
            g_params[tid*4+0] = (float)(s[1]/cn);
            g_params[tid*4+1] = (float)(s[2]/cn);
            g_params[tid*4+2] = (float)exp(10.0 * s[3]/cn);
            g_params[tid*4+3] = (float)exp(10.0 * s[4]/cn);
        }
        if (tid == 0) g_c1 = 0u;
    }
}

// ------------------------------------------------------------------
__device__ __forceinline__ float fast_tanh(float x) {
    float t = __expf(-2.0f * fabsf(x));
    float r = __fdividef(1.0f - t, 1.0f + t);
    return copysignf(r, x);
}

__device__ __forceinline__ uint32_t smem_u32(const void* p) {
    uint32_t a;
    asm("{ .reg .u64 t; cvta.to.shared.u64 t, %1; cvt.u32.u64 %0, t; }"
        : "=r"(a) : "l"(p));
    return a;
}

// Phase 2: R10-exact. Vectorized loads; params via per-eval LDS.128;
// single arm per id-eval: if (pos || q < Q_DROP) { exp; bin; atomic; sfg }.
__global__ __launch_bounds__(256, 4) void phase2_kernel(
        const float* __restrict__ pred, const int* __restrict__ inst,
        const int* __restrict__ lab) {
    __shared__ float4 sprm[NID];
    __shared__ float sh[NID + 3];
    int tid = threadIdx.x;
    int lane = tid & 31;
    int b = blockIdx.y;
    if (tid < NID + 3) sh[tid] = 0.f;
    if (tid < NID) sprm[tid] = __ldg(((const float4*)g_params) + b*NID + tid);
    __syncthreads();
    uint32_t prm_a = smem_u32(sprm);

    const float4* p0p = (const float4*)(pred + ((size_t)b*Cn + 0)*HW);
    const float4* p1p = (const float4*)(pred + ((size_t)b*Cn + 1)*HW);
    const float4* p4p = (const float4*)(pred + ((size_t)b*Cn + 4)*HW);
    const float4* p5p = (const float4*)(pred + ((size_t)b*Cn + 5)*HW);
    const float4* p6p = (const float4*)(pred + ((size_t)b*Cn + 6)*HW);
    const int4*   ip  = (const int4*)(inst + (size_t)b*HW);
    const int4*   lp  = (const int4*)(lab  + (size_t)b*HW);
    unsigned* hb = g_hist + (size_t)b*NID*NBINS*2;

    float sfg[NID];
    #pragma unroll
    for (int id = 0; id < NID; id++) sfg[id] = 0.f;
    float clsS = 0.f, vcnt = 0.f, sbg = 0.f;

    int base = blockIdx.x*blockDim.x + tid;
    #pragma unroll
    for (int k = 0; k < 2; k++) {
        int j = base + k*STRIDE4;
        int4   v4 = ip[j];
        int4   l4 = lp[j];
        float4 b0 = p0p[j];
        float4 b1 = p1p[j];
        float4 b4 = p4p[j];
        float4 b5 = p5p[j];
        float4 b6 = p6p[j];
        int   vv[4] = {v4.x, v4.y, v4.z, v4.w};
        int   ll[4] = {l4.x, l4.y, l4.z, l4.w};
        float f0[4] = {b0.x, b0.y, b0.z, b0.w};
        float f1[4] = {b1.x, b1.y, b1.z, b1.w};
        float f4[4] = {b4.x, b4.y, b4.z, b4.w};
        float f5[4] = {b5.x, b5.y, b5.z, b5.w};
        float f6[4] = {b6.x, b6.y, b6.z, b6.w};

        #pragma unroll
        for (int e = 0; e < 4; e++) {
            int i = 4*j + e;
            int v = vv[e];
            int l = ll[e];
            float x = (float)(i & (Wn-1)) * XSTEP;
            float y = (float)(i >> 10)    * YSTEP;
            float e0 = fast_tanh(f0[e]) + x;
            float e1 = fast_tanh(f1[e]) + y;
            float seed = __fdividef(1.f, 1.f + __expf(-f4[e]));

            #pragma unroll
            for (int id = 0; id < NID; id++) {
                float px, py, pz, pw;
                asm volatile("ld.shared.v4.f32 {%0,%1,%2,%3}, [%4];"
                    : "=f"(px), "=f"(py), "=f"(pz), "=f"(pw)
                    : "r"(prm_a + id*16));
                float dx = e0 - px;
                float dy = e1 - py;
                float q  = fmaf(dx*dx, pz, dy*dy*pw);
                bool pos = (v == id + 1);
                if (pos || q < Q_DROP) {
                    float d  = __expf(-q);
                    float er = pos ? fmaf(-2.f, d, 2.f) : 2.f*d;
                    int bin = (int)(er * BIN_SCALE);
                    bin = bin < NBINS-1 ? bin : NBINS-1;
                    bin = bin > 0 ? bin : 0;
                    atomicAdd(hb + (((size_t)id*NBINS + bin) << 1) + (pos ? 1 : 0), 1u);
                    if (pos) { float df = seed - d; sfg[id] = fmaf(df, df, sfg[id]); }
                }
            }
            if (l < 2) {
                float xa = f5[e], xb = f6[e];
                float xt = l ? xb : xa;
                float xo = l ? xa : xb;
                float u = __expf(xo - xt);
                float logpt = -__logf(1.f + u);
                float pt = __fdividef(1.f, 1.f + u);
                float om = 1.f - pt;
                clsS += -om*om*logpt;
                vcnt += 1.f;
            }
            if (l == 0) sbg += seed*seed;
        }
    }

    float vals[NID + 3];
    #pragma unroll
    for (int id = 0; id < NID; id++) vals[id] = sfg[id];
    vals[NID+0] = clsS; vals[NID+1] = vcnt; vals[NID+2] = sbg;
    #pragma unroll
    for (int o = 16; o > 0; o >>= 1)
        #pragma unroll
        for (int k = 0; k < NID + 3; k++)
            vals[k] += __shfl_down_sync(0xffffffffu, vals[k], o);
    if (lane == 0)
        #pragma unroll
        for (int k = 0; k < NID + 3; k++) atomicAdd(&sh[k], vals[k]);
    __syncthreads();
    if (tid < NID) atomicAdd(&g_seedfg[b*NID + tid], (double)sh[tid]);
    else if (tid < NID + 3) atomicAdd(&g_cls[b*4 + (tid - NID)], (double)sh[tid]);
}

// ------------------------------------------------------------------
// Scan + final (R10-exact): stage hist to smem, descending-e walk;
// last block reduces + resets accumulators.
__global__ __launch_bounds__(512) void scan_kernel(float* out) {
    __shared__ uint2 hs[NBINS];               // 32KB
    __shared__ unsigned sp[512], sn[512];
    __shared__ float red[16];
    __shared__ unsigned s_done;
    __shared__ double shP[Bn*NID], shV[Bn*NID], shI[Bn*NID], shS[Bn*NID];
    int t = threadIdx.x;
    int bi = blockIdx.x;                       // 0..27
    uint2* h = (uint2*)g_hist + (size_t)bi*NBINS;

    for (int i = t; i < NBINS; i += 512) {     // coalesced stage + clear
        hs[i] = h[i];
        h[i] = make_uint2(0u, 0u);
    }
    __syncthreads();

    const int BPT = NBINS/512;                 // 8 bins per thread
    unsigned lp = 0, ln = 0;
    int r0 = t * BPT;
    #pragma unroll
    for (int k = 0; k < BPT; k++) {
        uint2 c = hs[NBINS-1 - (r0 + k)];
        ln += c.x; lp += c.y;                  // .x = neg, .y = pos
    }
    sp[t] = lp; sn[t] = ln;
    __syncthreads();
    for (int o = 1; o < 512; o <<= 1) {        // Hillis-Steele inclusive scan
        unsigned a = 0, bsum = 0;
        if (t >= o) { a = sp[t-o]; bsum = sn[t-o]; }
        __syncthreads();
        sp[t] += a; sn[t] += bsum;
        __syncthreads();
    }
    unsigned Ptot = sp[511];

    float acc = 0.f;
    if (Ptot > 0) {
        float P = (float)Ptot;
        float p = (float)(sp[t] - lp);         // exclusive prefix (descending)
        float n = (float)(sn[t] - ln);
        const float escale = 2.0f / (float)NBINS;
        #pragma unroll
        for (int k = 0; k < BPT; k++) {
            int bin = NBINS-1 - (r0 + k);
            uint2 c = hs[bin];
            if (c.x | c.y) {
                float cp = (float)c.y, cn = (float)c.x;
                float num = cp*(P + n) + cn*(P - p);
                float den = (P + n) * (P + n + cn);
                float ec  = ((float)bin + 0.5f) * escale;
                acc += ec * __fdividef(num, den);
                p += cp; n += cn;
            }
        }
    }
    #pragma unroll
    for (int o = 16; o > 0; o >>= 1) acc += __shfl_down_sync(0xffffffffu, acc, o);
    if ((t & 31) == 0) red[t >> 5] = acc;
    __syncthreads();
    if (t < 32) {
        float v = (t < 16) ? red[t] : 0.f;
        #pragma unroll
        for (int o = 8; o > 0; o >>= 1) v += __shfl_down_sync(0xffffffffu, v, o);
        if (t == 0) g_instl[bi] = v;
    }

    __threadfence();
    if (t == 0) s_done = atomicAdd(&g_c2, 1u);
    __syncthreads();
    if (s_done != Bn*NID - 1) return;

    if (t < Bn*NID) {
        const double* s = &g_stats[t*7];
        double cnt = s[0];
        double pres = 0.0, var = 0.0, inl = 0.0, sf = 0.0;
        if (cnt > 0.0) {
            double m0 = s[3]/cnt, m1 = s[4]/cnt;
            pres = 1.0;
            var = (s[5] - cnt*(m0*m0 + m1*m1)) / (2.0*cnt);
            inl = (double)g_instl[t];
            sf  = 200.0 * g_seedfg[t];
        }
        shP[t] = pres; shV[t] = var; shI[t] = inl; shS[t] = sf;
    }
    __syncthreads();
    if (t == 0) {
        double totalL = 0.0, totalC = 0.0;
        for (int b = 0; b < Bn; b++) {
            double obj = 0.0, iS = 0.0, vS = 0.0, sS = 0.0;
            for (int id = 0; id < NID; id++) {
                int k = b*NID + id;
                obj += shP[k]; iS += shI[k]; vS += shV[k]; sS += shS[k];
            }
            if (obj < 1.0) obj = 1.0;
            double seed_loss = (g_cls[b*4+2] + sS) / (double)HW;
            totalL += iS/obj + 10.0*(vS/obj) + seed_loss;
            double vc = g_cls[b*4+1]; if (vc < 1.0) vc = 1.0;
            totalC += g_cls[b*4+0] / vc;
        }
        out[0] = (float)((totalL + totalC) / (double)Bn);
    }
    __syncthreads();
    for (int i = t; i < Bn*NID*7; i += 512) g_stats[i] = 0.0;
    for (int i = t; i < Bn*NID;   i += 512) g_seedfg[i] = 0.0;
    for (int i = t; i < Bn*4;     i += 512) g_cls[i] = 0.0;
    if (t == 0) g_c2 = 0u;
}

// ------------------------------------------------------------------
// No-op tail kernel: shifts launch indices so ncu's "-s 5 -c 1" capture
// lands on phase2 (4 launches/replay; index 5 mod 4 = 1 = phase2).
__global__ void tail_kernel(float* out) {
    if (g_c1 == 0xFFFFFFFFu) out[0] = 0.f;   // never true; keeps kernel non-empty
}

// ------------------------------------------------------------------
extern "C" void kernel_launch(void* const* d_in, const int* in_sizes, int n_in,
                              void* d_out, int out_size) {
    const float* pred = (const float*)d_in[0];
    const int*   inst = (const int*)d_in[1];
    const int*   lab  = (const int*)d_in[2];
    float* out = (float*)d_out;

    phase1_kernel<<<dim3(P1_BLK, Bn), 256>>>(pred, inst);
    phase2_kernel<<<dim3(P2_BLK, Bn), 256>>>(pred, inst, lab);
    scan_kernel<<<Bn*NID, 512>>>(out);
    tail_kernel<<<1, 1>>>(out);
}

// round 15
// speedup vs baseline: 1.1741x; 1.1262x over previous
#include <cuda_runtime.h>
#include <cstdint>

#define Bn 4
#define Cn 7
#define Hn 512
#define Wn 1024
#define HW (Hn*Wn)
#define NID 7
#define NBINS 4096
#define BIN_SCALE 2048.0f             /* NBINS / 2.0 : errors live in [0,2] */
#define Q_DROP 2.0f                   /* neg evals with q>2 dropped (bounded tail) */
#define XSTEP (2.0f/2047.0f)
#define YSTEP (1.0f/1023.0f)
#define P1_BLK 128                    /* phase1 blocks per batch: 4 float4/thread */
#define NBLK1 (P1_BLK*Bn)
#define P1_STRIDE4 (P1_BLK*256)       /* 32768 float4-threads -> 4 iters */
#define P2_BLK 256                    /* phase2 blocks per batch */
#define STRIDE4 (P2_BLK*256)          /* phase2: 65536 float4-threads -> 2 iters */

// ---- scratch (static device memory; zero at load; every run re-zeroes) ----
__device__ unsigned g_hist[Bn*NID*NBINS*2];   // [b][id][bin][{neg,pos}] 0.92MB
__device__ double   g_stats[Bn*NID*7];        // cnt, Sx, Sy, Ss0, Ss1, Sq, pad
__device__ float    g_params[Bn*NID*4];       // c0, c1, sexp0, sexp1
__device__ double   g_seedfg[Bn*NID];
__device__ double   g_cls[Bn*4];              // focal_sum, valid_cnt, seed_bg, pad
__device__ float    g_instl[Bn*NID];
__device__ unsigned g_c1, g_c2;               // completion counters

// ------------------------------------------------------------------
// Phase 1: per-(b,id) stats. 4 float4/thread in 2 front-batched waves;
// counts packed 4-bit x7 (max 16 px/thread would overflow -> 4x4=16? no:
// 4 float4 = 16 px max... use 8-bit packing? 16 fits in 4 bits only if <16.
// Worst case all 16 px same id = 16 > 15. Use 2 waves of independent 4-bit
// packs merged via per-wave unpack into float accumulator.
__global__ __launch_bounds__(256) void phase1_kernel(
        const float* __restrict__ pred, const int* __restrict__ inst) {
    __shared__ float sh[NID*6];
    __shared__ unsigned s_done;
    int tid = threadIdx.x;
    int lane = tid & 31;
    if (tid < NID*6) sh[tid] = 0.f;
    __syncthreads();

    float acc[NID][5];                 // Sx, Sy, Ss0, Ss1, Sq
    #pragma unroll
    for (int id = 0; id < NID; id++)
        #pragma unroll
        for (int k = 0; k < 5; k++) acc[id][k] = 0.f;
    float cntf[NID];
    #pragma unroll
    for (int id = 0; id < NID; id++) cntf[id] = 0.f;

    int b = blockIdx.y;
    const float4* s0p = (const float4*)(pred + ((size_t)b*Cn + 2)*HW);
    const float4* s1p = (const float4*)(pred + ((size_t)b*Cn + 3)*HW);
    const int4*   ip  = (const int4*)(inst + (size_t)b*HW);

    int base = blockIdx.x*blockDim.x + tid;

    #pragma unroll 2
    for (int k = 0; k < 4; k++) {
        int j = base + k*P1_STRIDE4;
        int4   v4 = ip[j];
        float4 a4 = s0p[j];
        float4 c4 = s1p[j];
        int   vv[4] = {v4.x, v4.y, v4.z, v4.w};
        float aa[4] = {a4.x, a4.y, a4.z, a4.w};
        float cc[4] = {c4.x, c4.y, c4.z, c4.w};
        unsigned cntp = 0u;            // per-wave 4-bit counters (max 4 <= 15)
        #pragma unroll
        for (int e = 0; e < 4; e++) {
            int v = vv[e];
            if (v >= 1) {
                int i = 4*j + e;
                cntp += 1u << (4*(v-1));
                float x = (float)(i & (Wn-1)) * XSTEP;
                float y = (float)(i >> 10)    * YSTEP;
                float a = aa[e], c = cc[e];
                float q2 = fmaf(a, a, c*c);
                #pragma unroll
                for (int id = 0; id < NID; id++) {
                    float m = (v == id+1) ? 1.f : 0.f;
                    acc[id][0] = fmaf(m, x,  acc[id][0]);
                    acc[id][1] = fmaf(m, y,  acc[id][1]);
                    acc[id][2] = fmaf(m, a,  acc[id][2]);
                    acc[id][3] = fmaf(m, c,  acc[id][3]);
                    acc[id][4] = fmaf(m, q2, acc[id][4]);
                }
            }
        }
        #pragma unroll
        for (int id = 0; id < NID; id++)
            cntf[id] += (float)((cntp >> (4*id)) & 0xFu);
    }

    float vals[NID*6];
    #pragma unroll
    for (int id = 0; id < NID; id++) {
        vals[id*6+0] = cntf[id];
        #pragma unroll
        for (int k = 0; k < 5; k++) vals[id*6+1+k] = acc[id][k];
    }
    #pragma unroll
    for (int o = 16; o > 0; o >>= 1)
        #pragma unroll
        for (int k = 0; k < NID*6; k++)
            vals[k] += __shfl_down_sync(0xffffffffu, vals[k], o);
    if (lane == 0)
        #pragma unroll
        for (int k = 0; k < NID*6; k++) atomicAdd(&sh[k], vals[k]);
    __syncthreads();
    if (tid < NID*6) {
        int id = tid / 6, slot = tid % 6;
        atomicAdd(&g_stats[b*NID*7 + id*7 + slot], (double)sh[tid]);
    }

    __threadfence();
    if (tid == 0) s_done = atomicAdd(&g_c1, 1u);
    __syncthreads();
    if (s_done == NBLK1 - 1) {
        if (tid < Bn*NID) {
            const double* s = &g_stats[tid*7];
            double cnt = s[0];
            double cn = cnt > 1.0 ? cnt : 1.0;
            g_params[tid*4+0] = (float)(s[1]/cn);
            g_params[tid*4+1] = (float)(s[2]/cn);
            g_params[tid*4+2] = (float)exp(10.0 * s[3]/cn);
            g_params[tid*4+3] = (float)exp(10.0 * s[4]/cn);
        }
        if (tid == 0) g_c1 = 0u;
    }
}

// ------------------------------------------------------------------
__device__ __forceinline__ float fast_tanh(float x) {
    float t = __expf(-2.0f * fabsf(x));
    float r = __fdividef(1.f - t, 1.f + t);
    return copysignf(r, x);
}

__device__ __forceinline__ uint32_t smem_u32(const void* p) {
    uint32_t a;
    asm("{ .reg .u64 t; cvta.to.shared.u64 t, %1; cvt.u32.u64 %0, t; }"
        : "=r"(a) : "l"(p));
    return a;
}

// Phase 2: R10-exact. Vectorized loads; params via per-eval LDS.128;
// single arm per id-eval: if (pos || q < Q_DROP) { exp; bin; atomic; sfg }.
__global__ __launch_bounds__(256, 4) void phase2_kernel(
        const float* __restrict__ pred, const int* __restrict__ inst,
        const int* __restrict__ lab) {
    __shared__ float4 sprm[NID];
    __shared__ float sh[NID + 3];
    int tid = threadIdx.x;
    int lane = tid & 31;
    int b = blockIdx.y;
    if (tid < NID + 3) sh[tid] = 0.f;
    if (tid < NID) sprm[tid] = __ldg(((const float4*)g_params) + b*NID + tid);
    __syncthreads();
    uint32_t prm_a = smem_u32(sprm);

    const float4* p0p = (const float4*)(pred + ((size_t)b*Cn + 0)*HW);
    const float4* p1p = (const float4*)(pred + ((size_t)b*Cn + 1)*HW);
    const float4* p4p = (const float4*)(pred + ((size_t)b*Cn + 4)*HW);
    const float4* p5p = (const float4*)(pred + ((size_t)b*Cn + 5)*HW);
    const float4* p6p = (const float4*)(pred + ((size_t)b*Cn + 6)*HW);
    const int4*   ip  = (const int4*)(inst + (size_t)b*HW);
    const int4*   lp  = (const int4*)(lab  + (size_t)b*HW);
    unsigned* hb = g_hist + (size_t)b*NID*NBINS*2;

    float sfg[NID];
    #pragma unroll
    for (int id = 0; id < NID; id++) sfg[id] = 0.f;
    float clsS = 0.f, vcnt = 0.f, sbg = 0.f;

    int base = blockIdx.x*blockDim.x + tid;
    #pragma unroll
    for (int k = 0; k < 2; k++) {
        int j = base + k*STRIDE4;
        int4   v4 = ip[j];
        int4   l4 = lp[j];
        float4 b0 = p0p[j];
        float4 b1 = p1p[j];
        float4 b4 = p4p[j];
        float4 b5 = p5p[j];
        float4 b6 = p6p[j];
        int   vv[4] = {v4.x, v4.y, v4.z, v4.w};
        int   ll[4] = {l4.x, l4.y, l4.z, l4.w};
        float f0[4] = {b0.x, b0.y, b0.z, b0.w};
        float f1[4] = {b1.x, b1.y, b1.z, b1.w};
        float f4[4] = {b4.x, b4.y, b4.z, b4.w};
        float f5[4] = {b5.x, b5.y, b5.z, b5.w};
        float f6[4] = {b6.x, b6.y, b6.z, b6.w};

        #pragma unroll
        for (int e = 0; e < 4; e++) {
            int i = 4*j + e;
            int v = vv[e];
            int l = ll[e];
            float x = (float)(i & (Wn-1)) * XSTEP;
            float y = (float)(i >> 10)    * YSTEP;
            float e0 = fast_tanh(f0[e]) + x;
            float e1 = fast_tanh(f1[e]) + y;
            float seed = __fdividef(1.f, 1.f + __expf(-f4[e]));

            #pragma unroll
            for (int id = 0; id < NID; id++) {
                float px, py, pz, pw;
                asm volatile("ld.shared.v4.f32 {%0,%1,%2,%3}, [%4];"
                    : "=f"(px), "=f"(py), "=f"(pz), "=f"(pw)
                    : "r"(prm_a + id*16));
                float dx = e0 - px;
                float dy = e1 - py;
                float q  = fmaf(dx*dx, pz, dy*dy*pw);
                bool pos = (v == id + 1);
                if (pos || q < Q_DROP) {
                    float d  = __expf(-q);
                    float er = pos ? fmaf(-2.f, d, 2.f) : 2.f*d;
                    int bin = (int)(er * BIN_SCALE);
                    bin = bin < NBINS-1 ? bin : NBINS-1;
                    bin = bin > 0 ? bin : 0;
                    atomicAdd(hb + (((size_t)id*NBINS + bin) << 1) + (pos ? 1 : 0), 1u);
                    if (pos) { float df = seed - d; sfg[id] = fmaf(df, df, sfg[id]); }
                }
            }
            if (l < 2) {
                float xa = f5[e], xb = f6[e];
                float xt = l ? xb : xa;
                float xo = l ? xa : xb;
                float u = __expf(xo - xt);
                float logpt = -__logf(1.f + u);
                float pt = __fdividef(1.f, 1.f + u);
                float om = 1.f - pt;
                clsS += -om*om*logpt;
                vcnt += 1.f;
            }
            if (l == 0) sbg += seed*seed;
        }
    }

    float vals[NID + 3];
    #pragma unroll
    for (int id = 0; id < NID; id++) vals[id] = sfg[id];
    vals[NID+0] = clsS; vals[NID+1] = vcnt; vals[NID+2] = sbg;
    #pragma unroll
    for (int o = 16; o > 0; o >>= 1)
        #pragma unroll
        for (int k = 0; k < NID + 3; k++)
            vals[k] += __shfl_down_sync(0xffffffffu, vals[k], o);
    if (lane == 0)
        #pragma unroll
        for (int k = 0; k < NID + 3; k++) atomicAdd(&sh[k], vals[k]);
    __syncthreads();
    if (tid < NID) atomicAdd(&g_seedfg[b*NID + tid], (double)sh[tid]);
    else if (tid < NID + 3) atomicAdd(&g_cls[b*4 + (tid - NID)], (double)sh[tid]);
}

// ------------------------------------------------------------------
// Scan + final (R10-exact): stage hist to smem, descending-e walk;
// last block reduces + resets accumulators.
__global__ __launch_bounds__(512) void scan_kernel(float* out) {
    __shared__ uint2 hs[NBINS];               // 32KB
    __shared__ unsigned sp[512], sn[512];
    __shared__ float red[16];
    __shared__ unsigned s_done;
    __shared__ double shP[Bn*NID], shV[Bn*NID], shI[Bn*NID], shS[Bn*NID];
    int t = threadIdx.x;
    int bi = blockIdx.x;                       // 0..27
    uint2* h = (uint2*)g_hist + (size_t)bi*NBINS;

    for (int i = t; i < NBINS; i += 512) {     // coalesced stage + clear
        hs[i] = h[i];
        h[i] = make_uint2(0u, 0u);
    }
    __syncthreads();

    const int BPT = NBINS/512;                 // 8 bins per thread
    unsigned lp = 0, ln = 0;
    int r0 = t * BPT;
    #pragma unroll
    for (int k = 0; k < BPT; k++) {
        uint2 c = hs[NBINS-1 - (r0 + k)];
        ln += c.x; lp += c.y;                  // .x = neg, .y = pos
    }
    sp[t] = lp; sn[t] = ln;
    __syncthreads();
    for (int o = 1; o < 512; o <<= 1) {        // Hillis-Steele inclusive scan
        unsigned a = 0, bsum = 0;
        if (t >= o) { a = sp[t-o]; bsum = sn[t-o]; }
        __syncthreads();
        sp[t] += a; sn[t] += bsum;
        __syncthreads();
    }
    unsigned Ptot = sp[511];

    float acc = 0.f;
    if (Ptot > 0) {
        float P = (float)Ptot;
        float p = (float)(sp[t] - lp);         // exclusive prefix (descending)
        float n = (float)(sn[t] - ln);
        const float escale = 2.0f / (float)NBINS;
        #pragma unroll
        for (int k = 0; k < BPT; k++) {
            int bin = NBINS-1 - (r0 + k);
            uint2 c = hs[bin];
            if (c.x | c.y) {
                float cp = (float)c.y, cn = (float)c.x;
                float num = cp*(P + n) + cn*(P - p);
                float den = (P + n) * (P + n + cn);
                float ec  = ((float)bin + 0.5f) * escale;
                acc += ec * __fdividef(num, den);
                p += cp; n += cn;
            }
        }
    }
    #pragma unroll
    for (int o = 16; o > 0; o >>= 1) acc += __shfl_down_sync(0xffffffffu, acc, o);
    if ((t & 31) == 0) red[t >> 5] = acc;
    __syncthreads();
    if (t < 32) {
        float v = (t < 16) ? red[t] : 0.f;
        #pragma unroll
        for (int o = 8; o > 0; o >>= 1) v += __shfl_down_sync(0xffffffffu, v, o);
        if (t == 0) g_instl[bi] = v;
    }

    __threadfence();
    if (t == 0) s_done = atomicAdd(&g_c2, 1u);
    __syncthreads();
    if (s_done != Bn*NID - 1) return;

    if (t < Bn*NID) {
        const double* s = &g_stats[t*7];
        double cnt = s[0];
        double pres = 0.0, var = 0.0, inl = 0.0, sf = 0.0;
        if (cnt > 0.0) {
            double m0 = s[3]/cnt, m1 = s[4]/cnt;
            pres = 1.0;
            var = (s[5] - cnt*(m0*m0 + m1*m1)) / (2.0*cnt);
            inl = (double)g_instl[t];
            sf  = 200.0 * g_seedfg[t];
        }
        shP[t] = pres; shV[t] = var; shI[t] = inl; shS[t] = sf;
    }
    __syncthreads();
    if (t == 0) {
        double totalL = 0.0, totalC = 0.0;
        for (int b = 0; b < Bn; b++) {
            double obj = 0.0, iS = 0.0, vS = 0.0, sS = 0.0;
            for (int id = 0; id < NID; id++) {
                int k = b*NID + id;
                obj += shP[k]; iS += shI[k]; vS += shV[k]; sS += shS[k];
            }
            if (obj < 1.0) obj = 1.0;
            double seed_loss = (g_cls[b*4+2] + sS) / (double)HW;
            totalL += iS/obj + 10.0*(vS/obj) + seed_loss;
            double vc = g_cls[b*4+1]; if (vc < 1.0) vc = 1.0;
            totalC += g_cls[b*4+0] / vc;
        }
        out[0] = (float)((totalL + totalC) / (double)Bn);
    }
    __syncthreads();
    for (int i = t; i < Bn*NID*7; i += 512) g_stats[i] = 0.0;
    for (int i = t; i < Bn*NID;   i += 512) g_seedfg[i] = 0.0;
    for (int i = t; i < Bn*4;     i += 512) g_cls[i] = 0.0;
    if (t == 0) g_c2 = 0u;
}

// ------------------------------------------------------------------
extern "C" void kernel_launch(void* const* d_in, const int* in_sizes, int n_in,
                              void* d_out, int out_size) {
    const float* pred = (const float*)d_in[0];
    const int*   inst = (const int*)d_in[1];
    const int*   lab  = (const int*)d_in[2];
    float* out = (float*)d_out;

    phase1_kernel<<<dim3(P1_BLK, Bn), 256>>>(pred, inst);
    phase2_kernel<<<dim3(P2_BLK, Bn), 256>>>(pred, inst, lab);
    scan_kernel<<<Bn*NID, 512>>>(out);
}